// round 15
// baseline (speedup 1.0000x reference)
#include <cuda_runtime.h>
#include <cuda_fp16.h>
#include <cstdint>

#define DI __device__ __forceinline__

static constexpr int B_ = 4, H_ = 8, S_ = 2048, D_ = 1024, KQ_ = 128;
static constexpr int PGRID = 296;   // narrow kernel: 148 SMs x 2 CTAs
static constexpr int PGRID1 = 148;  // wide kernel: 1 CTA/SM

// ---------------- scratch (device globals; no allocations allowed) ----------------
__device__ __half g_MT[(size_t)H_ * D_ * D_];            // M^T[h][j][d]
__device__ __half g_TWo[(size_t)H_ * D_ * D_];           // Wo^T per head
__device__ __half g_WvH[(size_t)H_ * D_ * D_];           // Wv fp16
__device__ __half g_TWqk[(size_t)2 * B_ * H_ * KQ_ * D_];// Wq^T/Wk^T dup per (sel,b)
__device__ float  g_bqk[2 * B_ * H_ * KQ_];              // bq/bk dup per (sel,b)
__device__ __half g_yzh[(size_t)2 * B_ * S_ * D_];       // y fp16 | z fp16
__device__ __half g_QK[(size_t)2 * B_ * H_ * S_ * KQ_];  // Q | K
__device__ __half g_UT[(size_t)B_ * H_ * D_ * S_];       // U^T[b,h][j][t]
__device__ __half g_Ph[(size_t)B_ * H_ * S_ * S_];       // scores / P fp16
__device__ float g_cvec[D_];
__device__ float g_cpart[32 * D_];

// ---------------- helpers ----------------
DI uint32_t smem_u32(const void* p) {
    uint32_t a;
    asm("{ .reg .u64 t; cvta.to.shared.u64 t, %1; cvt.u32.u64 %0, t; }" : "=r"(a) : "l"(p));
    return a;
}
DI void mma_f16(float c[4], uint32_t a0, uint32_t a1, uint32_t a2, uint32_t a3,
                uint32_t b0, uint32_t b1) {
    asm volatile(
        "mma.sync.aligned.m16n8k16.row.col.f32.f16.f16.f32 "
        "{%0,%1,%2,%3}, {%4,%5,%6,%7}, {%8,%9}, {%0,%1,%2,%3};"
        : "+f"(c[0]), "+f"(c[1]), "+f"(c[2]), "+f"(c[3])
        : "r"(a0), "r"(a1), "r"(a2), "r"(a3), "r"(b0), "r"(b1));
}
DI void ldsm4(uint32_t r[4], uint32_t a) {
    asm volatile("ldmatrix.sync.aligned.m8n8.x4.shared.b16 {%0,%1,%2,%3}, [%4];"
                 : "=r"(r[0]), "=r"(r[1]), "=r"(r[2]), "=r"(r[3]) : "r"(a));
}
DI void cp16(uint32_t d, const void* s) {
    asm volatile("cp.async.cg.shared.global [%0], [%1], 16;" :: "r"(d), "l"(s));
}
DI void cp_commit() { asm volatile("cp.async.commit_group;" ::: "memory"); }

DI void cwrite(__half* p, float a, float b) {
    *reinterpret_cast<__half2*>(p) = __floats2half2_rn(a, b);
}
DI void cwrite(float* p, float a, float b) {
    *reinterpret_cast<float2*>(p) = make_float2(a, b);
}

// ====== NARROW: fp16 NT GEMM, 128x128 CTA, 128 thr (4 warps @ 64x64), 3-stage ======
template <typename CT>
__global__ __launch_bounds__(128, 2) void nt_gemm(
    const __half* __restrict__ Ag, const __half* __restrict__ Bg,
    CT* __restrict__ Cg, const float* __restrict__ bias,
    int kchunks, int lda, int ldb, int ldc,
    long long sA1, long long sA2, long long sB1, long long sB2,
    long long sC1, long long sC2, int Z2, long long sbias1, int sbias2, float alpha,
    int hshift, int sAh, int sBh,
    int ngx, int ngy, int ntiles)
{
    extern __shared__ __align__(128) uint32_t dyn_smem[];
    const uint32_t sb = smem_u32(dyn_smem);

    const int tid = threadIdx.x, lane = tid & 31, wid = tid >> 5;
    const int wm = (wid & 1) * 64, wn = (wid >> 1) * 64;
    const int g = lane >> 2, q = lane & 3;

    const int lc = tid & 7, lr0 = tid >> 3;
    const uint32_t dst0 = (uint32_t)((lr0 * 8 + (lc ^ (lr0 & 7))) << 4);

    const int l15 = lane & 15, hs = lane >> 4;
    uint32_t arow[4], axor[4], brow[4], bxor[4];
#pragma unroll
    for (int mt = 0; mt < 4; mt++) {
        int rr = wm + mt * 16 + l15;
        arow[mt] = (uint32_t)(rr * 128);
        axor[mt] = (uint32_t)(rr & 7);
    }
#pragma unroll
    for (int np = 0; np < 4; np++) {
        int nn = wn + np * 16 + l15;
        brow[np] = (uint32_t)(nn * 128);
        bxor[np] = (uint32_t)(nn & 7);
    }

    const int hmask = (hshift < 30) ? ((1 << hshift) - 1) : 0x3FFFFFFF;
    const int nxy = ngx * ngy;
    const uint32_t astep = (uint32_t)(16 * lda), bstep = (uint32_t)(16 * ldb);

    int i_tile = blockIdx.x, i_chunk = 0;
    const __half *iA = Ag, *iB = Bg;
    uint32_t abase = 0, bbase = 0;
    bool has_issue = (i_tile < ntiles);

    auto setupIssue = [&](int t) {
        const int tz = t / nxy, rxy = t - tz * nxy;
        const int tyv = rxy / ngx, txv = rxy - tyv * ngx;
        const int z1 = tz / Z2, z2 = tz - z1 * Z2;
        iA = Ag + z1 * sA1 + z2 * sA2;
        iB = Bg + z1 * sB1 + z2 * sB2;
        abase = (uint32_t)((tyv * 128 + lr0) * lda + lc * 8);
        bbase = (uint32_t)((txv * 128 + lr0) * ldb + lc * 8);
    };
    if (has_issue) setupIssue(i_tile);

    uint32_t gi = 0;
    auto issueOne = [&]() {
        const uint32_t st = gi % 3u;
        const uint32_t koA = (uint32_t)(i_chunk >> hshift) * (uint32_t)sAh +
                             (uint32_t)(i_chunk & hmask) * 64u;
        const uint32_t koB = (uint32_t)(i_chunk >> hshift) * (uint32_t)sBh +
                             (uint32_t)(i_chunk & hmask) * 64u;
        const __half* Ac = iA + koA + abase;
        const __half* Bc = iB + koB + bbase;
        const uint32_t a0 = sb + st * 32768 + dst0, b0 = a0 + 16384;
#pragma unroll
        for (int i = 0; i < 8; i++) {
            cp16(a0 + i * 2048, Ac + i * astep);
            cp16(b0 + i * 2048, Bc + i * bstep);
        }
        cp_commit();
        gi++;
        if (++i_chunk == kchunks) {
            i_chunk = 0;
            i_tile += gridDim.x;
            if (i_tile < ntiles) setupIssue(i_tile);
            else has_issue = false;
        }
    };
    if (has_issue) issueOne();
    if (has_issue) issueOne();

    uint32_t gc = 0;
    for (int ct = blockIdx.x; ct < ntiles; ct += gridDim.x) {
        const int tz = ct / nxy, rxy = ct - tz * nxy;
        const int tyv = rxy / ngx, txv = rxy - tyv * ngx;
        const int z1 = tz / Z2, z2 = tz - z1 * Z2;
        CT* C = Cg + z1 * sC1 + z2 * sC2;
        const int bm = tyv * 128, bn = txv * 128;

        float acc[4][8][4];
#pragma unroll
        for (int i = 0; i < 4; i++)
#pragma unroll
            for (int j = 0; j < 8; j++)
#pragma unroll
                for (int k = 0; k < 4; k++) acc[i][j][k] = 0.f;

        for (int c = 0; c < kchunks; c++) {
            if (gi > gc + 1)
                asm volatile("cp.async.wait_group 1;" ::: "memory");
            else
                asm volatile("cp.async.wait_group 0;" ::: "memory");
            __syncthreads();
            if (has_issue) issueOne();

            const uint32_t st = gc % 3u;
            const uint32_t aB = sb + st * 32768, bB = aB + 16384;
#pragma unroll
            for (int s = 0; s < 4; s++) {
                uint32_t af[4][4], bf[8][2];
                const uint32_t cc = (uint32_t)(2 * s + hs);
#pragma unroll
                for (int mt = 0; mt < 4; mt++)
                    ldsm4(af[mt], aB + arow[mt] + ((cc ^ axor[mt]) << 4));
#pragma unroll
                for (int np = 0; np < 4; np++) {
                    uint32_t t4[4];
                    ldsm4(t4, bB + brow[np] + ((cc ^ bxor[np]) << 4));
                    bf[2 * np][0] = t4[0];
                    bf[2 * np][1] = t4[2];
                    bf[2 * np + 1][0] = t4[1];
                    bf[2 * np + 1][1] = t4[3];
                }
#pragma unroll
                for (int mt = 0; mt < 4; mt++)
#pragma unroll
                    for (int nt = 0; nt < 8; nt++)
                        mma_f16(acc[mt][nt], af[mt][0], af[mt][1], af[mt][2], af[mt][3],
                                bf[nt][0], bf[nt][1]);
            }
            gc++;
        }

        const float* bp = bias ? bias + z1 * sbias1 + (long long)z2 * sbias2 : nullptr;
#pragma unroll
        for (int mt = 0; mt < 4; mt++) {
#pragma unroll
            for (int nt = 0; nt < 8; nt++) {
                int r = bm + wm + mt * 16 + g;
                int cc = bn + wn + nt * 8 + q * 2;
                float b0v = bp ? bp[cc] : 0.f;
                float b1v = bp ? bp[cc + 1] : 0.f;
                cwrite(C + (long long)r * ldc + cc,
                       alpha * acc[mt][nt][0] + b0v, alpha * acc[mt][nt][1] + b1v);
                cwrite(C + (long long)(r + 8) * ldc + cc,
                       alpha * acc[mt][nt][2] + b0v, alpha * acc[mt][nt][3] + b1v);
            }
        }
    }
}

// ====== WIDE: fp16 NT GEMM, 128x256 CTA, 256 thr (8 warps 2x4 @ 64x64), 3-stage ======
// Stage = A 16KB + B 32KB = 48KB; 3 stages = 144KB dynamic smem; 1 CTA/SM.
template <typename CT>
__global__ __launch_bounds__(256, 1) void nt_gemm_w(
    const __half* __restrict__ Ag, const __half* __restrict__ Bg,
    CT* __restrict__ Cg, const float* __restrict__ bias,
    int kchunks, int lda, int ldb, int ldc,
    long long sA1, long long sA2, long long sB1, long long sB2,
    long long sC1, long long sC2, int Z2, long long sbias1, int sbias2, float alpha,
    int hshift, int sAh, int sBh,
    int ngx, int ngy, int ntiles)
{
    extern __shared__ __align__(128) uint32_t dyn_smem[];
    const uint32_t sb = smem_u32(dyn_smem);

    const int tid = threadIdx.x, lane = tid & 31, wid = tid >> 5;
    const int wm = (wid & 1) * 64, wn = (wid >> 1) * 64;
    const int g = lane >> 2, q = lane & 3;

    const int lc = tid & 7, lr0 = tid >> 3;   // lr0 in 0..31
    const uint32_t dst0 = (uint32_t)((lr0 * 8 + (lc ^ (lr0 & 7))) << 4);

    const int l15 = lane & 15, hs = lane >> 4;
    uint32_t arow[4], axor[4], brow[4], bxor[4];
#pragma unroll
    for (int mt = 0; mt < 4; mt++) {
        int rr = wm + mt * 16 + l15;
        arow[mt] = (uint32_t)(rr * 128);
        axor[mt] = (uint32_t)(rr & 7);
    }
#pragma unroll
    for (int np = 0; np < 4; np++) {
        int nn = wn + np * 16 + l15;
        brow[np] = (uint32_t)(nn * 128);
        bxor[np] = (uint32_t)(nn & 7);
    }

    const int hmask = (hshift < 30) ? ((1 << hshift) - 1) : 0x3FFFFFFF;
    const int nxy = ngx * ngy;
    const uint32_t astep = (uint32_t)(32 * lda), bstep = (uint32_t)(32 * ldb);

    int i_tile = blockIdx.x, i_chunk = 0;
    const __half *iA = Ag, *iB = Bg;
    uint32_t abase = 0, bbase = 0;
    bool has_issue = (i_tile < ntiles);

    auto setupIssue = [&](int t) {
        const int tz = t / nxy, rxy = t - tz * nxy;
        const int tyv = rxy / ngx, txv = rxy - tyv * ngx;
        const int z1 = tz / Z2, z2 = tz - z1 * Z2;
        iA = Ag + z1 * sA1 + z2 * sA2;
        iB = Bg + z1 * sB1 + z2 * sB2;
        abase = (uint32_t)((tyv * 128 + lr0) * lda + lc * 8);
        bbase = (uint32_t)((txv * 256 + lr0) * ldb + lc * 8);
    };
    if (has_issue) setupIssue(i_tile);

    uint32_t gi = 0;
    auto issueOne = [&]() {
        const uint32_t st = gi % 3u;
        const uint32_t koA = (uint32_t)(i_chunk >> hshift) * (uint32_t)sAh +
                             (uint32_t)(i_chunk & hmask) * 64u;
        const uint32_t koB = (uint32_t)(i_chunk >> hshift) * (uint32_t)sBh +
                             (uint32_t)(i_chunk & hmask) * 64u;
        const __half* Ac = iA + koA + abase;
        const __half* Bc = iB + koB + bbase;
        const uint32_t a0 = sb + st * 49152 + dst0, b0 = a0 + 16384;
#pragma unroll
        for (int i = 0; i < 4; i++)
            cp16(a0 + i * 4096, Ac + i * astep);
#pragma unroll
        for (int i = 0; i < 8; i++)
            cp16(b0 + i * 4096, Bc + i * bstep);
        cp_commit();
        gi++;
        if (++i_chunk == kchunks) {
            i_chunk = 0;
            i_tile += gridDim.x;
            if (i_tile < ntiles) setupIssue(i_tile);
            else has_issue = false;
        }
    };
    if (has_issue) issueOne();
    if (has_issue) issueOne();

    uint32_t gc = 0;
    for (int ct = blockIdx.x; ct < ntiles; ct += gridDim.x) {
        const int tz = ct / nxy, rxy = ct - tz * nxy;
        const int tyv = rxy / ngx, txv = rxy - tyv * ngx;
        const int z1 = tz / Z2, z2 = tz - z1 * Z2;
        CT* C = Cg + z1 * sC1 + z2 * sC2;
        const int bm = tyv * 128, bn = txv * 256;

        float acc[4][8][4];
#pragma unroll
        for (int i = 0; i < 4; i++)
#pragma unroll
            for (int j = 0; j < 8; j++)
#pragma unroll
                for (int k = 0; k < 4; k++) acc[i][j][k] = 0.f;

        for (int c = 0; c < kchunks; c++) {
            if (gi > gc + 1)
                asm volatile("cp.async.wait_group 1;" ::: "memory");
            else
                asm volatile("cp.async.wait_group 0;" ::: "memory");
            __syncthreads();
            if (has_issue) issueOne();

            const uint32_t st = gc % 3u;
            const uint32_t aB = sb + st * 49152, bB = aB + 16384;
#pragma unroll
            for (int s = 0; s < 4; s++) {
                uint32_t af[4][4], bf[8][2];
                const uint32_t cc = (uint32_t)(2 * s + hs);
#pragma unroll
                for (int mt = 0; mt < 4; mt++)
                    ldsm4(af[mt], aB + arow[mt] + ((cc ^ axor[mt]) << 4));
#pragma unroll
                for (int np = 0; np < 4; np++) {
                    uint32_t t4[4];
                    ldsm4(t4, bB + brow[np] + ((cc ^ bxor[np]) << 4));
                    bf[2 * np][0] = t4[0];
                    bf[2 * np][1] = t4[2];
                    bf[2 * np + 1][0] = t4[1];
                    bf[2 * np + 1][1] = t4[3];
                }
#pragma unroll
                for (int mt = 0; mt < 4; mt++)
#pragma unroll
                    for (int nt = 0; nt < 8; nt++)
                        mma_f16(acc[mt][nt], af[mt][0], af[mt][1], af[mt][2], af[mt][3],
                                bf[nt][0], bf[nt][1]);
            }
            gc++;
        }

        const float* bp = bias ? bias + z1 * sbias1 + (long long)z2 * sbias2 : nullptr;
#pragma unroll
        for (int mt = 0; mt < 4; mt++) {
#pragma unroll
            for (int nt = 0; nt < 8; nt++) {
                int r = bm + wm + mt * 16 + g;
                int cc = bn + wn + nt * 8 + q * 2;
                float b0v = bp ? bp[cc] : 0.f;
                float b1v = bp ? bp[cc + 1] : 0.f;
                cwrite(C + (long long)r * ldc + cc,
                       alpha * acc[mt][nt][0] + b0v, alpha * acc[mt][nt][1] + b1v);
                cwrite(C + (long long)(r + 8) * ldc + cc,
                       alpha * acc[mt][nt][2] + b0v, alpha * acc[mt][nt][3] + b1v);
            }
        }
    }
}

// ============ fused prepass ============
__global__ __launch_bounds__(256) void prepass_k(
    const float* __restrict__ z, const float* __restrict__ y,
    const float* __restrict__ Wv, const float* __restrict__ Wo,
    const float* __restrict__ Wq, const float* __restrict__ Wk,
    const float* __restrict__ bv, const float* __restrict__ bq,
    const float* __restrict__ bk)
{
    __shared__ float t[32][33];
    const int b = blockIdx.x, tid = threadIdx.x;

    if (b < 24576) {
        const float* in;
        __half* out;
        int i;
        if (b < 8192)       { in = y;  out = g_yzh;                         i = b * 256 + tid; }
        else if (b < 16384) { in = z;  out = g_yzh + (size_t)B_ * S_ * D_;  i = (b - 8192) * 256 + tid; }
        else                { in = Wv; out = g_WvH;                         i = (b - 16384) * 256 + tid; }
        float4 v = reinterpret_cast<const float4*>(in)[i];
        __half2 h0 = __floats2half2_rn(v.x, v.y);
        __half2 h1 = __floats2half2_rn(v.z, v.w);
        uint2 u;
        u.x = *reinterpret_cast<uint32_t*>(&h0);
        u.y = *reinterpret_cast<uint32_t*>(&h1);
        reinterpret_cast<uint2*>(out)[i] = u;
        return;
    }
    if (b < 32768) {   // trans Wo
        const int idx = b - 24576;
        const int h = idx >> 10, rxy = idx & 1023;
        const int byi = rxy >> 5, bxi = rxy & 31;
        const float* ip = Wo + (size_t)h * D_ * D_;
        __half* op = g_TWo + (size_t)h * D_ * D_;
        int bx = bxi * 32, by = byi * 32;
        int tx = tid & 31, ty = tid >> 5;
#pragma unroll
        for (int j = 0; j < 32; j += 8)
            t[ty + j][tx] = ip[(size_t)(by + ty + j) * D_ + bx + tx];
        __syncthreads();
#pragma unroll
        for (int j = 0; j < 32; j += 8)
            op[(size_t)(bx + ty + j) * D_ + by + tx] = __float2half(t[tx][ty + j]);
        return;
    }
    if (b < 34816) {   // trans Wq/Wk, dup x4 b-slots
        const int sel = (b < 33792) ? 0 : 1;
        const int idx = b - (sel ? 33792 : 32768);
        const float* in = sel ? Wk : Wq;
        const int h = idx >> 7, rxy = idx & 127;
        const int byi = rxy >> 2, bxi = rxy & 3;
        const float* ip = in + (size_t)h * D_ * KQ_;
        int bx = bxi * 32, by = byi * 32;
        int tx = tid & 31, ty = tid >> 5;
#pragma unroll
        for (int j = 0; j < 32; j += 8)
            t[ty + j][tx] = ip[(size_t)(by + ty + j) * KQ_ + bx + tx];
        __syncthreads();
#pragma unroll
        for (int j = 0; j < 32; j += 8) {
            __half hv = __float2half(t[tx][ty + j]);
            size_t ro = (size_t)(bx + ty + j) * D_ + by + tx;
#pragma unroll
            for (int bb = 0; bb < 4; bb++) {
                __half* op = g_TWqk + ((size_t)((sel * 4 + bb) * 8 + h)) * (KQ_ * D_);
                op[ro] = hv;
            }
        }
        return;
    }
    if (b < 34824) {   // bqk
        int idx2 = (b - 34816) * 256 + tid;
        int sel = idx2 >> 10, h = (idx2 >> 7) & 7, j = idx2 & 127;
        float v = sel ? bk[h * KQ_ + j] : bq[h * KQ_ + j];
#pragma unroll
        for (int bb = 0; bb < 4; bb++)
            g_bqk[((sel * 4 + bb) * 8 + h) * KQ_ + j] = v;
        return;
    }
    {   // cvec partials
        const int idx = b - 34824;
        const int j = (idx & 3) * 256 + tid;
        const int r0 = (idx >> 2) * 256;
        float acc = 0.f;
        for (int r = r0; r < r0 + 256; r++) acc += bv[r] * Wo[(size_t)r * D_ + j];
        g_cpart[(idx >> 2) * D_ + j] = acc;
    }
}

__global__ void cvec_final_k(const float* __restrict__ bo) {
    int j = blockIdx.x * 256 + threadIdx.x;
    float acc = bo[j];
    for (int r = 0; r < 32; r++) acc += g_cpart[r * D_ + j];
    g_cvec[j] = acc;
}

// ------- row softmax on fp16 scores, in place -------
__global__ __launch_bounds__(256) void softmax_k() {
    __half* row = g_Ph + (size_t)blockIdx.x * S_;
    int tid = threadIdx.x;
    uint4 u = *reinterpret_cast<const uint4*>(row + tid * 8);
    float v[8];
    {
        __half2* hp = reinterpret_cast<__half2*>(&u);
#pragma unroll
        for (int i = 0; i < 4; i++) {
            float2 f = __half22float2(hp[i]);
            v[2 * i] = f.x;
            v[2 * i + 1] = f.y;
        }
    }
    float mx = -1e30f;
#pragma unroll
    for (int i = 0; i < 8; i++) mx = fmaxf(mx, v[i]);
#pragma unroll
    for (int o = 16; o > 0; o >>= 1) mx = fmaxf(mx, __shfl_xor_sync(0xffffffffu, mx, o));
    __shared__ float red[8];
    if ((tid & 31) == 0) red[tid >> 5] = mx;
    __syncthreads();
    mx = red[0];
#pragma unroll
    for (int wi = 1; wi < 8; wi++) mx = fmaxf(mx, red[wi]);

    float s = 0.f;
#pragma unroll
    for (int i = 0; i < 8; i++) {
        v[i] = exp2f((v[i] - mx) * 1.4426950408889634f);
        s += v[i];
    }
#pragma unroll
    for (int o = 16; o > 0; o >>= 1) s += __shfl_xor_sync(0xffffffffu, s, o);
    __syncthreads();
    if ((tid & 31) == 0) red[tid >> 5] = s;
    __syncthreads();
    s = 0.f;
#pragma unroll
    for (int wi = 0; wi < 8; wi++) s += red[wi];
    float inv = 1.f / s;

    __half2 p0 = __floats2half2_rn(v[0] * inv, v[1] * inv);
    __half2 p1 = __floats2half2_rn(v[2] * inv, v[3] * inv);
    __half2 p2 = __floats2half2_rn(v[4] * inv, v[5] * inv);
    __half2 p3 = __floats2half2_rn(v[6] * inv, v[7] * inv);
    uint4 o;
    o.x = *reinterpret_cast<uint32_t*>(&p0);
    o.y = *reinterpret_cast<uint32_t*>(&p1);
    o.z = *reinterpret_cast<uint32_t*>(&p2);
    o.w = *reinterpret_cast<uint32_t*>(&p3);
    *reinterpret_cast<uint4*>(row + tid * 8) = o;
}

// ---------------- launch ----------------
static constexpr int GSMEM = 98304;    // narrow: 3 stages x 32KB
static constexpr int WSMEM = 147456;   // wide:   3 stages x 48KB

extern "C" void kernel_launch(void* const* d_in, const int* in_sizes, int n_in,
                              void* d_out, int out_size) {
    const float* z  = (const float*)d_in[0];
    const float* y  = (const float*)d_in[1];
    const float* Wq = (const float*)d_in[2];
    const float* bq = (const float*)d_in[3];
    const float* Wk = (const float*)d_in[4];
    const float* bk = (const float*)d_in[5];
    const float* Wv = (const float*)d_in[6];
    const float* bv = (const float*)d_in[7];
    const float* Wo = (const float*)d_in[8];
    const float* bo = (const float*)d_in[9];
    float* out = (float*)d_out;

    __half *pMT, *pTWo, *pWvH, *pTWqk, *pyzh, *pQK, *pUT, *pPh;
    float *pc, *pbqk;
    cudaGetSymbolAddress((void**)&pMT, g_MT);
    cudaGetSymbolAddress((void**)&pTWo, g_TWo);
    cudaGetSymbolAddress((void**)&pWvH, g_WvH);
    cudaGetSymbolAddress((void**)&pTWqk, g_TWqk);
    cudaGetSymbolAddress((void**)&pyzh, g_yzh);
    cudaGetSymbolAddress((void**)&pQK, g_QK);
    cudaGetSymbolAddress((void**)&pUT, g_UT);
    cudaGetSymbolAddress((void**)&pPh, g_Ph);
    cudaGetSymbolAddress((void**)&pc, g_cvec);
    cudaGetSymbolAddress((void**)&pbqk, g_bqk);

    cudaFuncSetAttribute(nt_gemm<__half>,
                         cudaFuncAttributeMaxDynamicSharedMemorySize, GSMEM);
    cudaFuncSetAttribute(nt_gemm_w<__half>,
                         cudaFuncAttributeMaxDynamicSharedMemorySize, WSMEM);
    cudaFuncSetAttribute(nt_gemm_w<float>,
                         cudaFuncAttributeMaxDynamicSharedMemorySize, WSMEM);

    // 1) fused prepass + bias fold
    prepass_k<<<34952, 256>>>(z, y, Wv, Wo, Wq, Wk, bv, bq, bk);
    cvec_final_k<<<4, 256>>>(bo);

    // 2) M^T[h] = TWo[h] @ WvH[h]^T              wide: 256 tiles (4n x 8m x 8h)
    nt_gemm_w<__half><<<PGRID1, 256, WSMEM>>>(
        pTWo, pWvH, pMT, nullptr, 16, 1024, 1024, 1024,
        0, (long long)D_ * D_, 0, (long long)D_ * D_, 0, (long long)D_ * D_,
        8, 0, 0, 1.f, 30, 0, 0, 4, 8, 256);

    // 3) QK: [sel,b,h]: C = yzh[sel*4+b] @ TWqk[sel,b,h]^T + bqk   narrow: 1024 tiles
    nt_gemm<__half><<<PGRID, 128, GSMEM>>>(
        pyzh, pTWqk, pQK, pbqk, 16, 1024, 1024, 128,
        (long long)S_ * D_, 0,
        (long long)8 * KQ_ * D_, (long long)KQ_ * D_,
        (long long)H_ * S_ * KQ_, (long long)S_ * KQ_,
        8, 8 * KQ_, KQ_, 1.f, 30, 0, 0, 1, 16, 1024);

    // 4) U^T[b,h] = MT[h] @ zh[b]^T              wide: 2048 tiles (8n x 8m x 32)
    nt_gemm_w<__half><<<PGRID1, 256, WSMEM>>>(
        pMT, pyzh + (size_t)B_ * S_ * D_, pUT, nullptr, 16, 1024, 1024, 2048,
        0, (long long)D_ * D_, (long long)S_ * D_, 0,
        (long long)H_ * D_ * S_, (long long)D_ * S_, 8, 0, 0, 1.f, 30, 0, 0,
        8, 8, 2048);

    // 5) scores = (Q @ K^T)/sqrt(128) fp16       narrow: 8192 tiles, K=2 chunks
    nt_gemm<__half><<<PGRID, 128, GSMEM>>>(
        pQK, pQK + (size_t)B_ * H_ * S_ * KQ_, pPh, nullptr, 2, 128, 128, 2048,
        0, (long long)S_ * KQ_,
        0, (long long)S_ * KQ_,
        0, (long long)S_ * S_,
        32, 0, 0, 0.08838834764831845f, 30, 0, 0, 16, 16, 8192);

    // 6) softmax rows (fp16 in place)
    softmax_k<<<B_ * H_ * S_, 256>>>();

    // 7) out = sum_h P_h @ UT_h^T + cvec         wide: 256 tiles (4n x 16m x 4b)
    nt_gemm_w<float><<<PGRID1, 256, WSMEM>>>(
        pPh, pUT, out, pc, 256, 2048, 2048, 1024,
        0, (long long)H_ * S_ * S_, 0, (long long)H_ * D_ * S_,
        0, (long long)S_ * D_, 4, 0, 0, 1.f,
        5, S_ * S_, D_ * S_, 4, 16, 256);
}

// round 17
// speedup vs baseline: 1.0364x; 1.0364x over previous
#include <cuda_runtime.h>
#include <cuda_fp16.h>
#include <cstdint>

#define DI __device__ __forceinline__

static constexpr int B_ = 4, H_ = 8, S_ = 2048, D_ = 1024, KQ_ = 128;
static constexpr int PGRID = 296;   // 148 SMs x 2 CTAs

// ---------------- scratch (device globals; no allocations allowed) ----------------
__device__ __half g_MT[(size_t)H_ * D_ * D_];            // M^T[h][j][d]
__device__ __half g_TWo[(size_t)H_ * D_ * D_];           // Wo^T per head
__device__ __half g_WvH[(size_t)H_ * D_ * D_];           // Wv fp16
__device__ __half g_TWqk[(size_t)2 * B_ * H_ * KQ_ * D_];// Wq^T/Wk^T dup per (sel,b)
__device__ float  g_bqk[2 * B_ * H_ * KQ_];              // bq/bk dup per (sel,b)
__device__ __half g_yzh[(size_t)2 * B_ * S_ * D_];       // y fp16 | z fp16
__device__ __half g_QK[(size_t)2 * B_ * H_ * S_ * KQ_];  // Q | K
__device__ __half g_UT[(size_t)B_ * H_ * D_ * S_];       // U^T[b,h][j][t]
__device__ __half g_Ph[(size_t)B_ * H_ * S_ * S_];       // scores / P fp16
__device__ float g_cvec[D_];
__device__ float g_cpart[32 * D_];

// ---------------- helpers ----------------
DI uint32_t smem_u32(const void* p) {
    uint32_t a;
    asm("{ .reg .u64 t; cvta.to.shared.u64 t, %1; cvt.u32.u64 %0, t; }" : "=r"(a) : "l"(p));
    return a;
}
DI void mma_f16(float c[4], uint32_t a0, uint32_t a1, uint32_t a2, uint32_t a3,
                uint32_t b0, uint32_t b1) {
    asm volatile(
        "mma.sync.aligned.m16n8k16.row.col.f32.f16.f16.f32 "
        "{%0,%1,%2,%3}, {%4,%5,%6,%7}, {%8,%9}, {%0,%1,%2,%3};"
        : "+f"(c[0]), "+f"(c[1]), "+f"(c[2]), "+f"(c[3])
        : "r"(a0), "r"(a1), "r"(a2), "r"(a3), "r"(b0), "r"(b1));
}
DI void ldsm4(uint32_t r[4], uint32_t a) {
    asm volatile("ldmatrix.sync.aligned.m8n8.x4.shared.b16 {%0,%1,%2,%3}, [%4];"
                 : "=r"(r[0]), "=r"(r[1]), "=r"(r[2]), "=r"(r[3]) : "r"(a));
}
DI void cp16(uint32_t d, const void* s) {
    asm volatile("cp.async.cg.shared.global [%0], [%1], 16;" :: "r"(d), "l"(s));
}
DI void cp_commit() { asm volatile("cp.async.commit_group;" ::: "memory"); }

DI uint32_t pack2(float a, float b) {
    __half2 h = __floats2half2_rn(a, b);
    return *reinterpret_cast<uint32_t*>(&h);
}
DI void sts32(uint32_t a, uint32_t v) {
    asm volatile("st.shared.b32 [%0], %1;" :: "r"(a), "r"(v) : "memory");
}
DI void lds128(uint32_t r[4], uint32_t a) {
    asm volatile("ld.shared.v4.u32 {%0,%1,%2,%3}, [%4];"
                 : "=r"(r[0]), "=r"(r[1]), "=r"(r[2]), "=r"(r[3]) : "r"(a));
}
DI void cwrite(float* p, float a, float b) {
    *reinterpret_cast<float2*>(p) = make_float2(a, b);
}

// ====== fp16 NT GEMM, 128x128 CTA, 128 thr (4 warps @ 64x64), K-chunk 64 halves,
// ====== 3-stage cp.async, persistent, continuous cross-tile pipeline ======
// fp16-C path stages the output tile in the free smem stage for full-line STG.
template <typename CT>
__global__ __launch_bounds__(128, 2) void nt_gemm(
    const __half* __restrict__ Ag, const __half* __restrict__ Bg,
    CT* __restrict__ Cg, const float* __restrict__ bias,
    int kchunks, int lda, int ldb, int ldc,
    long long sA1, long long sA2, long long sB1, long long sB2,
    long long sC1, long long sC2, int Z2, long long sbias1, int sbias2, float alpha,
    int hshift, int sAh, int sBh,
    int ngx, int ngy, int ntiles)
{
    extern __shared__ __align__(128) uint32_t dyn_smem[];
    const uint32_t sb = smem_u32(dyn_smem);

    const int tid = threadIdx.x, lane = tid & 31, wid = tid >> 5;
    const int wm = (wid & 1) * 64, wn = (wid >> 1) * 64;
    const int g = lane >> 2, q = lane & 3;

    const int lc = tid & 7, lr0 = tid >> 3;
    const uint32_t dst0 = (uint32_t)((lr0 * 8 + (lc ^ (lr0 & 7))) << 4);

    const int l15 = lane & 15, hs = lane >> 4;
    uint32_t arow[4], axor[4], brow[4], bxor[4];
#pragma unroll
    for (int mt = 0; mt < 4; mt++) {
        int rr = wm + mt * 16 + l15;
        arow[mt] = (uint32_t)(rr * 128);
        axor[mt] = (uint32_t)(rr & 7);
    }
#pragma unroll
    for (int np = 0; np < 4; np++) {
        int nn = wn + np * 16 + l15;
        brow[np] = (uint32_t)(nn * 128);
        bxor[np] = (uint32_t)(nn & 7);
    }

    const int hmask = (hshift < 30) ? ((1 << hshift) - 1) : 0x3FFFFFFF;
    const int nxy = ngx * ngy;
    const uint32_t astep = (uint32_t)(16 * lda), bstep = (uint32_t)(16 * ldb);

    int i_tile = blockIdx.x, i_chunk = 0;
    const __half *iA = Ag, *iB = Bg;
    uint32_t abase = 0, bbase = 0;
    bool has_issue = (i_tile < ntiles);

    auto setupIssue = [&](int t) {
        const int tz = t / nxy, rxy = t - tz * nxy;
        const int tyv = rxy / ngx, txv = rxy - tyv * ngx;
        const int z1 = tz / Z2, z2 = tz - z1 * Z2;
        iA = Ag + z1 * sA1 + z2 * sA2;
        iB = Bg + z1 * sB1 + z2 * sB2;
        abase = (uint32_t)((tyv * 128 + lr0) * lda + lc * 8);
        bbase = (uint32_t)((txv * 128 + lr0) * ldb + lc * 8);
    };
    if (has_issue) setupIssue(i_tile);

    uint32_t gi = 0;
    auto issueOne = [&]() {
        const uint32_t st = gi % 3u;
        const uint32_t koA = (uint32_t)(i_chunk >> hshift) * (uint32_t)sAh +
                             (uint32_t)(i_chunk & hmask) * 64u;
        const uint32_t koB = (uint32_t)(i_chunk >> hshift) * (uint32_t)sBh +
                             (uint32_t)(i_chunk & hmask) * 64u;
        const __half* Ac = iA + koA + abase;
        const __half* Bc = iB + koB + bbase;
        const uint32_t a0 = sb + st * 32768 + dst0, b0 = a0 + 16384;
#pragma unroll
        for (int i = 0; i < 8; i++) {
            cp16(a0 + i * 2048, Ac + i * astep);
            cp16(b0 + i * 2048, Bc + i * bstep);
        }
        cp_commit();
        gi++;
        if (++i_chunk == kchunks) {
            i_chunk = 0;
            i_tile += gridDim.x;
            if (i_tile < ntiles) setupIssue(i_tile);
            else has_issue = false;
        }
    };
    if (has_issue) issueOne();
    if (has_issue) issueOne();

    uint32_t gc = 0;
    for (int ct = blockIdx.x; ct < ntiles; ct += gridDim.x) {
        const int tz = ct / nxy, rxy = ct - tz * nxy;
        const int tyv = rxy / ngx, txv = rxy - tyv * ngx;
        const int z1 = tz / Z2, z2 = tz - z1 * Z2;
        CT* C = Cg + z1 * sC1 + z2 * sC2;
        const int bm = tyv * 128, bn = txv * 128;

        float acc[4][8][4];
#pragma unroll
        for (int i = 0; i < 4; i++)
#pragma unroll
            for (int j = 0; j < 8; j++)
#pragma unroll
                for (int k = 0; k < 4; k++) acc[i][j][k] = 0.f;

        for (int c = 0; c < kchunks; c++) {
            if (gi > gc + 1)
                asm volatile("cp.async.wait_group 1;" ::: "memory");
            else
                asm volatile("cp.async.wait_group 0;" ::: "memory");
            __syncthreads();
            if (has_issue) issueOne();

            const uint32_t st = gc % 3u;
            const uint32_t aB = sb + st * 32768, bB = aB + 16384;
#pragma unroll
            for (int s = 0; s < 4; s++) {
                uint32_t af[4][4], bf[8][2];
                const uint32_t cc = (uint32_t)(2 * s + hs);
#pragma unroll
                for (int mt = 0; mt < 4; mt++)
                    ldsm4(af[mt], aB + arow[mt] + ((cc ^ axor[mt]) << 4));
#pragma unroll
                for (int np = 0; np < 4; np++) {
                    uint32_t t4[4];
                    ldsm4(t4, bB + brow[np] + ((cc ^ bxor[np]) << 4));
                    bf[2 * np][0] = t4[0];
                    bf[2 * np][1] = t4[2];
                    bf[2 * np + 1][0] = t4[1];
                    bf[2 * np + 1][1] = t4[3];
                }
#pragma unroll
                for (int mt = 0; mt < 4; mt++)
#pragma unroll
                    for (int nt = 0; nt < 8; nt++)
                        mma_f16(acc[mt][nt], af[mt][0], af[mt][1], af[mt][2], af[mt][3],
                                bf[nt][0], bf[nt][1]);
            }
            gc++;
        }

        const float* bp = bias ? bias + z1 * sbias1 + (long long)z2 * sbias2 : nullptr;

        if constexpr (sizeof(CT) == 2) {
            // ---- fp16 epilogue: stage tile in smem, then full-line STG ----
            // Staging stage = (gc+2)%3 == (gc-1)%3, i.e. the stage the FINAL chunk was
            // computed from.  The __syncthreads() below is load-bearing: it ensures all
            // warps finished their ldmatrix reads of that stage before any warp
            // overwrites it with output halves (missing barrier = round-16 bug).
            // Safe vs. the issue cursor: next cp.async into this stage is chunk gc+2,
            // issued only after the next tile's first barrier, which every thread's
            // copy-out precedes.
            __syncthreads();
            const uint32_t stg = sb + ((gc + 2u) % 3u) * 32768u;
#pragma unroll
            for (int mt = 0; mt < 4; mt++) {
#pragma unroll
                for (int nt = 0; nt < 8; nt++) {
                    const int col = wn + nt * 8 + q * 2;
                    const uint32_t cpart = (uint32_t)((col & 7) * 2);
                    const int r0 = wm + mt * 16 + g;
                    float b0v = bp ? bp[col] : 0.f;
                    float b1v = bp ? bp[col + 1] : 0.f;
                    uint32_t a0 = stg + r0 * 256 + ((((col >> 3) ^ (r0 & 15))) << 4) + cpart;
                    sts32(a0, pack2(alpha * acc[mt][nt][0] + b0v, alpha * acc[mt][nt][1] + b1v));
                    const int r1 = r0 + 8;
                    uint32_t a1 = stg + r1 * 256 + ((((col >> 3) ^ (r1 & 15))) << 4) + cpart;
                    sts32(a1, pack2(alpha * acc[mt][nt][2] + b0v, alpha * acc[mt][nt][3] + b1v));
                }
            }
            __syncthreads();
            const int row0 = tid >> 4, seg = tid & 15;
#pragma unroll
            for (int it = 0; it < 16; it++) {
                const int row = row0 + it * 8;
                uint32_t v[4];
                lds128(v, stg + row * 256 + ((seg ^ (row & 15)) << 4));
                *reinterpret_cast<uint4*>(
                    reinterpret_cast<__half*>(C) + (long long)(bm + row) * ldc + bn + seg * 8) =
                    make_uint4(v[0], v[1], v[2], v[3]);
            }
        } else {
            // ---- fp32 epilogue: direct float2 stores (4 lanes = 32B contiguous) ----
#pragma unroll
            for (int mt = 0; mt < 4; mt++) {
#pragma unroll
                for (int nt = 0; nt < 8; nt++) {
                    int r = bm + wm + mt * 16 + g;
                    int cc = bn + wn + nt * 8 + q * 2;
                    float b0v = bp ? bp[cc] : 0.f;
                    float b1v = bp ? bp[cc + 1] : 0.f;
                    cwrite(reinterpret_cast<float*>(C) + (long long)r * ldc + cc,
                           alpha * acc[mt][nt][0] + b0v, alpha * acc[mt][nt][1] + b1v);
                    cwrite(reinterpret_cast<float*>(C) + (long long)(r + 8) * ldc + cc,
                           alpha * acc[mt][nt][2] + b0v, alpha * acc[mt][nt][3] + b1v);
                }
            }
        }
    }
}

// ============ fused prepass ============
__global__ __launch_bounds__(256) void prepass_k(
    const float* __restrict__ z, const float* __restrict__ y,
    const float* __restrict__ Wv, const float* __restrict__ Wo,
    const float* __restrict__ Wq, const float* __restrict__ Wk,
    const float* __restrict__ bv, const float* __restrict__ bq,
    const float* __restrict__ bk)
{
    __shared__ float t[32][33];
    const int b = blockIdx.x, tid = threadIdx.x;

    if (b < 24576) {
        const float* in;
        __half* out;
        int i;
        if (b < 8192)       { in = y;  out = g_yzh;                         i = b * 256 + tid; }
        else if (b < 16384) { in = z;  out = g_yzh + (size_t)B_ * S_ * D_;  i = (b - 8192) * 256 + tid; }
        else                { in = Wv; out = g_WvH;                         i = (b - 16384) * 256 + tid; }
        float4 v = reinterpret_cast<const float4*>(in)[i];
        __half2 h0 = __floats2half2_rn(v.x, v.y);
        __half2 h1 = __floats2half2_rn(v.z, v.w);
        uint2 u;
        u.x = *reinterpret_cast<uint32_t*>(&h0);
        u.y = *reinterpret_cast<uint32_t*>(&h1);
        reinterpret_cast<uint2*>(out)[i] = u;
        return;
    }
    if (b < 32768) {   // trans Wo
        const int idx = b - 24576;
        const int h = idx >> 10, rxy = idx & 1023;
        const int byi = rxy >> 5, bxi = rxy & 31;
        const float* ip = Wo + (size_t)h * D_ * D_;
        __half* op = g_TWo + (size_t)h * D_ * D_;
        int bx = bxi * 32, by = byi * 32;
        int tx = tid & 31, ty = tid >> 5;
#pragma unroll
        for (int j = 0; j < 32; j += 8)
            t[ty + j][tx] = ip[(size_t)(by + ty + j) * D_ + bx + tx];
        __syncthreads();
#pragma unroll
        for (int j = 0; j < 32; j += 8)
            op[(size_t)(bx + ty + j) * D_ + by + tx] = __float2half(t[tx][ty + j]);
        return;
    }
    if (b < 34816) {   // trans Wq/Wk, dup x4 b-slots
        const int sel = (b < 33792) ? 0 : 1;
        const int idx = b - (sel ? 33792 : 32768);
        const float* in = sel ? Wk : Wq;
        const int h = idx >> 7, rxy = idx & 127;
        const int byi = rxy >> 2, bxi = rxy & 3;
        const float* ip = in + (size_t)h * D_ * KQ_;
        int bx = bxi * 32, by = byi * 32;
        int tx = tid & 31, ty = tid >> 5;
#pragma unroll
        for (int j = 0; j < 32; j += 8)
            t[ty + j][tx] = ip[(size_t)(by + ty + j) * KQ_ + bx + tx];
        __syncthreads();
#pragma unroll
        for (int j = 0; j < 32; j += 8) {
            __half hv = __float2half(t[tx][ty + j]);
            size_t ro = (size_t)(bx + ty + j) * D_ + by + tx;
#pragma unroll
            for (int bb = 0; bb < 4; bb++) {
                __half* op = g_TWqk + ((size_t)((sel * 4 + bb) * 8 + h)) * (KQ_ * D_);
                op[ro] = hv;
            }
        }
        return;
    }
    if (b < 34824) {   // bqk
        int idx2 = (b - 34816) * 256 + tid;
        int sel = idx2 >> 10, h = (idx2 >> 7) & 7, j = idx2 & 127;
        float v = sel ? bk[h * KQ_ + j] : bq[h * KQ_ + j];
#pragma unroll
        for (int bb = 0; bb < 4; bb++)
            g_bqk[((sel * 4 + bb) * 8 + h) * KQ_ + j] = v;
        return;
    }
    {   // cvec partials
        const int idx = b - 34824;
        const int j = (idx & 3) * 256 + tid;
        const int r0 = (idx >> 2) * 256;
        float acc = 0.f;
        for (int r = r0; r < r0 + 256; r++) acc += bv[r] * Wo[(size_t)r * D_ + j];
        g_cpart[(idx >> 2) * D_ + j] = acc;
    }
}

__global__ void cvec_final_k(const float* __restrict__ bo) {
    int j = blockIdx.x * 256 + threadIdx.x;
    float acc = bo[j];
    for (int r = 0; r < 32; r++) acc += g_cpart[r * D_ + j];
    g_cvec[j] = acc;
}

// ------- row softmax on fp16 scores, in place -------
__global__ __launch_bounds__(256) void softmax_k() {
    __half* row = g_Ph + (size_t)blockIdx.x * S_;
    int tid = threadIdx.x;
    uint4 u = *reinterpret_cast<const uint4*>(row + tid * 8);
    float v[8];
    {
        __half2* hp = reinterpret_cast<__half2*>(&u);
#pragma unroll
        for (int i = 0; i < 4; i++) {
            float2 f = __half22float2(hp[i]);
            v[2 * i] = f.x;
            v[2 * i + 1] = f.y;
        }
    }
    float mx = -1e30f;
#pragma unroll
    for (int i = 0; i < 8; i++) mx = fmaxf(mx, v[i]);
#pragma unroll
    for (int o = 16; o > 0; o >>= 1) mx = fmaxf(mx, __shfl_xor_sync(0xffffffffu, mx, o));
    __shared__ float red[8];
    if ((tid & 31) == 0) red[tid >> 5] = mx;
    __syncthreads();
    mx = red[0];
#pragma unroll
    for (int wi = 1; wi < 8; wi++) mx = fmaxf(mx, red[wi]);

    float s = 0.f;
#pragma unroll
    for (int i = 0; i < 8; i++) {
        v[i] = exp2f((v[i] - mx) * 1.4426950408889634f);
        s += v[i];
    }
#pragma unroll
    for (int o = 16; o > 0; o >>= 1) s += __shfl_xor_sync(0xffffffffu, s, o);
    __syncthreads();
    if ((tid & 31) == 0) red[tid >> 5] = s;
    __syncthreads();
    s = 0.f;
#pragma unroll
    for (int wi = 0; wi < 8; wi++) s += red[wi];
    float inv = 1.f / s;

    __half2 p0 = __floats2half2_rn(v[0] * inv, v[1] * inv);
    __half2 p1 = __floats2half2_rn(v[2] * inv, v[3] * inv);
    __half2 p2 = __floats2half2_rn(v[4] * inv, v[5] * inv);
    __half2 p3 = __floats2half2_rn(v[6] * inv, v[7] * inv);
    uint4 o;
    o.x = *reinterpret_cast<uint32_t*>(&p0);
    o.y = *reinterpret_cast<uint32_t*>(&p1);
    o.z = *reinterpret_cast<uint32_t*>(&p2);
    o.w = *reinterpret_cast<uint32_t*>(&p3);
    *reinterpret_cast<uint4*>(row + tid * 8) = o;
}

// ---------------- launch ----------------
static constexpr int GSMEM = 98304;   // 3 stages x 32KB

extern "C" void kernel_launch(void* const* d_in, const int* in_sizes, int n_in,
                              void* d_out, int out_size) {
    const float* z  = (const float*)d_in[0];
    const float* y  = (const float*)d_in[1];
    const float* Wq = (const float*)d_in[2];
    const float* bq = (const float*)d_in[3];
    const float* Wk = (const float*)d_in[4];
    const float* bk = (const float*)d_in[5];
    const float* Wv = (const float*)d_in[6];
    const float* bv = (const float*)d_in[7];
    const float* Wo = (const float*)d_in[8];
    const float* bo = (const float*)d_in[9];
    float* out = (float*)d_out;

    __half *pMT, *pTWo, *pWvH, *pTWqk, *pyzh, *pQK, *pUT, *pPh;
    float *pc, *pbqk;
    cudaGetSymbolAddress((void**)&pMT, g_MT);
    cudaGetSymbolAddress((void**)&pTWo, g_TWo);
    cudaGetSymbolAddress((void**)&pWvH, g_WvH);
    cudaGetSymbolAddress((void**)&pTWqk, g_TWqk);
    cudaGetSymbolAddress((void**)&pyzh, g_yzh);
    cudaGetSymbolAddress((void**)&pQK, g_QK);
    cudaGetSymbolAddress((void**)&pUT, g_UT);
    cudaGetSymbolAddress((void**)&pPh, g_Ph);
    cudaGetSymbolAddress((void**)&pc, g_cvec);
    cudaGetSymbolAddress((void**)&pbqk, g_bqk);

    cudaFuncSetAttribute(nt_gemm<__half>,
                         cudaFuncAttributeMaxDynamicSharedMemorySize, GSMEM);
    cudaFuncSetAttribute(nt_gemm<float>,
                         cudaFuncAttributeMaxDynamicSharedMemorySize, GSMEM);

    // 1) fused prepass + bias fold
    prepass_k<<<34952, 256>>>(z, y, Wv, Wo, Wq, Wk, bv, bq, bk);
    cvec_final_k<<<4, 256>>>(bo);

    // 2) M^T[h] = TWo[h] @ WvH[h]^T              512 tiles
    nt_gemm<__half><<<PGRID, 128, GSMEM>>>(
        pTWo, pWvH, pMT, nullptr, 16, 1024, 1024, 1024,
        0, (long long)D_ * D_, 0, (long long)D_ * D_, 0, (long long)D_ * D_,
        8, 0, 0, 1.f, 30, 0, 0, 8, 8, 512);

    // 3) QK: [sel,b,h]: C = yzh[sel*4+b] @ TWqk[sel,b,h]^T + bqk   1024 tiles
    nt_gemm<__half><<<PGRID, 128, GSMEM>>>(
        pyzh, pTWqk, pQK, pbqk, 16, 1024, 1024, 128,
        (long long)S_ * D_, 0,
        (long long)8 * KQ_ * D_, (long long)KQ_ * D_,
        (long long)H_ * S_ * KQ_, (long long)S_ * KQ_,
        8, 8 * KQ_, KQ_, 1.f, 30, 0, 0, 1, 16, 1024);

    // 4) U^T[b,h] = MT[h] @ zh[b]^T              4096 tiles
    nt_gemm<__half><<<PGRID, 128, GSMEM>>>(
        pMT, pyzh + (size_t)B_ * S_ * D_, pUT, nullptr, 16, 1024, 1024, 2048,
        0, (long long)D_ * D_, (long long)S_ * D_, 0,
        (long long)H_ * D_ * S_, (long long)D_ * S_, 8, 0, 0, 1.f, 30, 0, 0,
        16, 8, 4096);

    // 5) scores = (Q @ K^T)/sqrt(128) fp16       8192 tiles, K=2 chunks
    nt_gemm<__half><<<PGRID, 128, GSMEM>>>(
        pQK, pQK + (size_t)B_ * H_ * S_ * KQ_, pPh, nullptr, 2, 128, 128, 2048,
        0, (long long)S_ * KQ_,
        0, (long long)S_ * KQ_,
        0, (long long)S_ * S_,
        32, 0, 0, 0.08838834764831845f, 30, 0, 0, 16, 16, 8192);

    // 6) softmax rows (fp16 in place)
    softmax_k<<<B_ * H_ * S_, 256>>>();

    // 7) out = sum_h P_h @ UT_h^T + cvec         512 tiles, K=256 chunks (32/head)
    nt_gemm<float><<<PGRID, 128, GSMEM>>>(
        pPh, pUT, out, pc, 256, 2048, 2048, 1024,
        0, (long long)H_ * S_ * S_, 0, (long long)H_ * D_ * S_,
        0, (long long)S_ * D_, 4, 0, 0, 1.f,
        5, S_ * S_, D_ * S_, 8, 16, 512);
}